// round 4
// baseline (speedup 1.0000x reference)
#include <cuda_runtime.h>
#include <cstdint>

// Fused attention with softmax over the HEAD axis (dim=1 quirk).
// B=2, H=8, S=4096, d=64. fp32 end-to-end SIMT baseline.
//
// Layout notes:
//  Q: [B,H,S,64]   K: [B,H,64,S] (pre-transposed)   V: [B,H,S,64]
//  Output reshape in the reference is a RAW reshape of [B,H,S,d], so we
//  write O in [B,H,S,64] contiguous order directly.
//
// Per CTA: one (b, 32-query block), all 8 heads. 512 threads = 16 warps;
// warp w handles head (w>>1), s-half (w&1). Loop over 32-key tiles:
//   1. stage K[8][64][32] and V[8][32][64] tiles in smem
//   2. E[h][s][t] = (Q*scale) @ K  (register micro-tile 2s x 8t per lane)
//   3. softmax over h in smem (local per (s,t) -- no running state needed)
//   4. O[h][s][:] += A @ V  (register micro-tile 2s x 16dv per lane)

namespace {
constexpr int NB = 2, NH = 8, SEQ = 4096, D = 64;
constexpr int S_TILE = 32, T_TILE = 32;
constexpr int ES_LD  = 34;      // padded score-row stride (8B-aligned, bank-spread)
constexpr int THREADS = 512;
constexpr int SMEM_FLOATS = NH*D*S_TILE      // Qs (k-major, scaled)
                          + NH*D*T_TILE      // Ks
                          + NH*T_TILE*D      // Vs
                          + NH*S_TILE*ES_LD; // Es (scores -> weights in place)
constexpr int SMEM_BYTES = SMEM_FLOATS * 4;  // 231424 B <= 232448 B cap
}

__global__ __launch_bounds__(THREADS, 1)
void attn_headsoftmax_kernel(const float* __restrict__ Q,
                             const float* __restrict__ K,
                             const float* __restrict__ V,
                             float* __restrict__ O)
{
    extern __shared__ float smem[];
    float* Qs = smem;                   // [NH][D][S_TILE]  (k-major, s contiguous)
    float* Ks = Qs + NH*D*S_TILE;       // [NH][D][T_TILE]  (k-major, t contiguous)
    float* Vs = Ks + NH*D*T_TILE;       // [NH][T_TILE][D]
    float* Es = Vs + NH*T_TILE*D;       // [NH][S_TILE][ES_LD]

    const int tid  = threadIdx.x;
    const int wid  = tid >> 5;
    const int lane = tid & 31;
    const int b    = blockIdx.x >> 7;             // 128 s-blocks per batch
    const int s0   = (blockIdx.x & 127) * S_TILE;

    const int h     = wid >> 1;                   // warp's head
    const int sbase = (wid & 1) * 16;             // warp's s-half within tile
    const int sg    = lane >> 2;                  // 8 s-groups
    const int tg    = lane & 3;                   // 4 t/dv-groups
    const int sA    = sbase + sg * 2;             // lane's first of 2 s rows

    const float scale = 0.044194173824159216f;    // 1/sqrt(512)

    // ---- stage Q tile once: scaled + transposed to [h][k][s] ----
    {
        const int r    = tid >> 1;                // 0..255 == h*32 + s
        const int half = tid & 1;                 // which 32-wide k half
        const int qh = r >> 5, qs = r & 31;
        const float* src = Q + (((size_t)(b*NH + qh))*SEQ + (size_t)(s0 + qs))*D + half*32;
        #pragma unroll
        for (int m = 0; m < 8; ++m) {
            float4 v = *(const float4*)(src + m*4);
            const int k0 = half*32 + m*4;
            Qs[(qh*D + k0+0)*S_TILE + qs] = v.x * scale;
            Qs[(qh*D + k0+1)*S_TILE + qs] = v.y * scale;
            Qs[(qh*D + k0+2)*S_TILE + qs] = v.z * scale;
            Qs[(qh*D + k0+3)*S_TILE + qs] = v.w * scale;
        }
    }

    float oacc[2][16];                            // lane's O accumulator: 2s x 16dv
    #pragma unroll
    for (int i = 0; i < 2; ++i)
        #pragma unroll
        for (int j = 0; j < 16; ++j) oacc[i][j] = 0.f;

    const size_t kb = ((size_t)b * NH * D) * SEQ; // base of this batch's K rows

    for (int t0g = 0; t0g < SEQ; t0g += T_TILE) {
        __syncthreads();  // previous tile fully consumed (and Qs visible on iter 0)

        // ---- stage K tile: 512 rows (h*64+k) x 32 t, coalesced float4 ----
        #pragma unroll
        for (int i = 0; i < 8; ++i) {
            const int f   = tid + i*THREADS;      // 0..4095 float4s
            const int row = f >> 3;               // h*64 + k
            const int seg = (f & 7) * 4;
            float4 v = *(const float4*)(K + kb + (size_t)row*SEQ + t0g + seg);
            *(float4*)&Ks[row*T_TILE + seg] = v;
        }
        // ---- stage V tile: 256 rows (h*32+t) x 64 dv ----
        #pragma unroll
        for (int i = 0; i < 8; ++i) {
            const int f   = tid + i*THREADS;
            const int row = f >> 4;               // h*32 + t
            const int col = (f & 15) * 4;
            const int vh = row >> 5, vt = row & 31;
            float4 v = *(const float4*)(V + (((size_t)(b*NH + vh))*SEQ + (size_t)(t0g + vt))*D + col);
            *(float4*)&Vs[row*D + col] = v;
        }
        __syncthreads();

        // ---- E[h][s][t] = (Q*scale) @ K : per-lane 2s x 8t micro-tile ----
        {
            float e0[8], e1[8];
            #pragma unroll
            for (int j = 0; j < 8; ++j) { e0[j] = 0.f; e1[j] = 0.f; }
            const float* qb  = Qs + h*D*S_TILE + sA;
            const float* kbp = Ks + h*D*T_TILE + tg*8;
            #pragma unroll 8
            for (int k = 0; k < D; ++k) {
                float2 q  = *(const float2*)(qb  + k*S_TILE);
                float4 b0 = *(const float4*)(kbp + k*T_TILE);
                float4 b1 = *(const float4*)(kbp + k*T_TILE + 4);
                e0[0] += q.x*b0.x; e0[1] += q.x*b0.y; e0[2] += q.x*b0.z; e0[3] += q.x*b0.w;
                e0[4] += q.x*b1.x; e0[5] += q.x*b1.y; e0[6] += q.x*b1.z; e0[7] += q.x*b1.w;
                e1[0] += q.y*b0.x; e1[1] += q.y*b0.y; e1[2] += q.y*b0.z; e1[3] += q.y*b0.w;
                e1[4] += q.y*b1.x; e1[5] += q.y*b1.y; e1[6] += q.y*b1.z; e1[7] += q.y*b1.w;
            }
            float* eb = Es + (h*S_TILE + sA)*ES_LD + tg*8;
            *(float2*)(eb+0) = make_float2(e0[0], e0[1]);
            *(float2*)(eb+2) = make_float2(e0[2], e0[3]);
            *(float2*)(eb+4) = make_float2(e0[4], e0[5]);
            *(float2*)(eb+6) = make_float2(e0[6], e0[7]);
            float* eb1 = eb + ES_LD;
            *(float2*)(eb1+0) = make_float2(e1[0], e1[1]);
            *(float2*)(eb1+2) = make_float2(e1[2], e1[3]);
            *(float2*)(eb1+4) = make_float2(e1[4], e1[5]);
            *(float2*)(eb1+6) = make_float2(e1[6], e1[7]);
        }
        __syncthreads();

        // ---- softmax over the 8 heads, in place (local per (s,t)) ----
        {
            const int ss = tid >> 4;              // s in 0..31
            const int tt = (tid & 15) * 2;        // pair of t positions
            float2 ev[8];
            #pragma unroll
            for (int hh = 0; hh < 8; ++hh)
                ev[hh] = *(const float2*)&Es[(hh*S_TILE + ss)*ES_LD + tt];
            float m0 = ev[0].x, m1 = ev[0].y;
            #pragma unroll
            for (int hh = 1; hh < 8; ++hh) { m0 = fmaxf(m0, ev[hh].x); m1 = fmaxf(m1, ev[hh].y); }
            float sum0 = 0.f, sum1 = 0.f;
            #pragma unroll
            for (int hh = 0; hh < 8; ++hh) {
                ev[hh].x = __expf(ev[hh].x - m0);
                ev[hh].y = __expf(ev[hh].y - m1);
                sum0 += ev[hh].x; sum1 += ev[hh].y;
            }
            const float r0 = __fdividef(1.f, sum0);
            const float r1 = __fdividef(1.f, sum1);
            #pragma unroll
            for (int hh = 0; hh < 8; ++hh)
                *(float2*)&Es[(hh*S_TILE + ss)*ES_LD + tt] =
                    make_float2(ev[hh].x * r0, ev[hh].y * r1);
        }
        __syncthreads();

        // ---- O += A @ V : per-lane 2s x 16dv micro-tile (dv = tg*4 + 16j + r) ----
        {
            const float* ab0 = Es + (h*S_TILE + sA)*ES_LD;
            const float* ab1 = ab0 + ES_LD;
            const float* vb  = Vs + h*T_TILE*D + tg*4;
            #pragma unroll 4
            for (int t = 0; t < T_TILE; ++t) {
                const float a0 = ab0[t];
                const float a1 = ab1[t];
                const float* vr = vb + t*D;
                #pragma unroll
                for (int j = 0; j < 4; ++j) {
                    float4 v = *(const float4*)(vr + j*16);
                    oacc[0][j*4+0] += a0*v.x; oacc[0][j*4+1] += a0*v.y;
                    oacc[0][j*4+2] += a0*v.z; oacc[0][j*4+3] += a0*v.w;
                    oacc[1][j*4+0] += a1*v.x; oacc[1][j*4+1] += a1*v.y;
                    oacc[1][j*4+2] += a1*v.z; oacc[1][j*4+3] += a1*v.w;
                }
            }
        }
    }

    // ---- writeback: raw [B,H,S,64] order == reference's .reshape view ----
    #pragma unroll
    for (int i = 0; i < 2; ++i) {
        float* dst = O + (((size_t)(b*NH + h))*SEQ + (size_t)(s0 + sA + i))*D + tg*4;
        #pragma unroll
        for (int j = 0; j < 4; ++j)
            *(float4*)(dst + j*16) = make_float4(oacc[i][j*4+0], oacc[i][j*4+1],
                                                 oacc[i][j*4+2], oacc[i][j*4+3]);
    }
}

extern "C" void kernel_launch(void* const* d_in, const int* in_sizes, int n_in,
                              void* d_out, int out_size) {
    (void)in_sizes; (void)n_in; (void)out_size;
    const float* Q = (const float*)d_in[0];
    const float* K = (const float*)d_in[1];
    const float* V = (const float*)d_in[2];
    float* O = (float*)d_out;
    cudaFuncSetAttribute(attn_headsoftmax_kernel,
                         cudaFuncAttributeMaxDynamicSharedMemorySize, SMEM_BYTES);
    attn_headsoftmax_kernel<<<NB * (SEQ / S_TILE), THREADS, SMEM_BYTES>>>(Q, K, V, O);
}